// round 1
// baseline (speedup 1.0000x reference)
#include <cuda_runtime.h>

#define HID   1024
#define HEADS 16
#define DK    64
#define BATCH 2
#define SEQ   2048
#define MROWS (BATCH*SEQ)      // 4096
#define QK_SCALE 0.125f        // 1/sqrt(64)

// Scratch (allocation-free rule: __device__ globals)
__device__ float g_qh[BATCH*HEADS*SEQ*DK];   // [B,h,S,d] 16 MB
__device__ float g_kh[BATCH*HEADS*SEQ*DK];
__device__ float g_vh[BATCH*HEADS*SEQ*DK];
__device__ float g_ctx[MROWS*HID];           // attention output, [B,S,H] 16 MB

// ---------------------------------------------------------------------------
// C[M,N] = X[M,K] @ W[N,K]^T + bias   (M=4096, N=K=1024)
// SCATTER=1: write into [B, head, S, d] layout. SCATTER=0: plain row-major.
// 64x64 block tile, BK=16, 256 threads, 4x4 per-thread microtile.
// ---------------------------------------------------------------------------
template<int SCATTER>
__global__ __launch_bounds__(256)
void gemm_kernel(const float* __restrict__ X, const float* __restrict__ W,
                 const float* __restrict__ bias, float* __restrict__ out)
{
    __shared__ float As[16][68];   // [k][m], +4 pad: conflict-free transposed store,
    __shared__ float Bs[16][68];   // 16B-aligned float4 rows (68*4 % 16 == 0)
    const int K  = HID;
    const int m0 = blockIdx.y << 6;
    const int n0 = blockIdx.x << 6;
    const int tid = threadIdx.x;
    const int tx = tid & 15;         // N within tile (x4)
    const int ty = tid >> 4;         // M within tile (x4)
    const int lr = tid >> 2;         // load row 0..63
    const int lc = (tid & 3) << 2;   // load k-offset {0,4,8,12}

    const float* Ap = X + (size_t)(m0 + lr) * K + lc;
    const float* Bp = W + (size_t)(n0 + lr) * K + lc;

    float acc[4][4] = {};
    float4 a_pre = *(const float4*)Ap;     // software prefetch (global->reg)
    float4 b_pre = *(const float4*)Bp;

    for (int kt = 0; kt < K / 16; ++kt) {
        As[lc+0][lr] = a_pre.x; As[lc+1][lr] = a_pre.y;
        As[lc+2][lr] = a_pre.z; As[lc+3][lr] = a_pre.w;
        Bs[lc+0][lr] = b_pre.x; Bs[lc+1][lr] = b_pre.y;
        Bs[lc+2][lr] = b_pre.z; Bs[lc+3][lr] = b_pre.w;
        __syncthreads();
        if (kt + 1 < K / 16) {
            a_pre = *(const float4*)(Ap + (size_t)(kt + 1) * 16);
            b_pre = *(const float4*)(Bp + (size_t)(kt + 1) * 16);
        }
        #pragma unroll
        for (int kk = 0; kk < 16; ++kk) {
            float4 a = *(const float4*)&As[kk][ty << 2];
            float4 b = *(const float4*)&Bs[kk][tx << 2];
            float av[4] = {a.x, a.y, a.z, a.w};
            float bv[4] = {b.x, b.y, b.z, b.w};
            #pragma unroll
            for (int i = 0; i < 4; ++i)
                #pragma unroll
                for (int j = 0; j < 4; ++j)
                    acc[i][j] += av[i] * bv[j];
        }
        __syncthreads();
    }

    float bb[4];
    #pragma unroll
    for (int j = 0; j < 4; ++j) bb[j] = bias[n0 + (tx << 2) + j];

    if (SCATTER) {
        // n0 is 64-aligned -> whole block maps to one head
        const int hh = n0 >> 6;
        const int d0 = tx << 2;
        #pragma unroll
        for (int i = 0; i < 4; ++i) {
            int m    = m0 + (ty << 2) + i;
            int bidx = m >> 11;            // S = 2048 = 2^11
            int s    = m & (SEQ - 1);
            float4 o = make_float4(acc[i][0]+bb[0], acc[i][1]+bb[1],
                                   acc[i][2]+bb[2], acc[i][3]+bb[3]);
            *(float4*)&out[(size_t)((bidx*HEADS + hh)*SEQ + s) * DK + d0] = o;
        }
    } else {
        #pragma unroll
        for (int i = 0; i < 4; ++i) {
            int m = m0 + (ty << 2) + i;
            float4 o = make_float4(acc[i][0]+bb[0], acc[i][1]+bb[1],
                                   acc[i][2]+bb[2], acc[i][3]+bb[3]);
            *(float4*)&out[(size_t)m * HID + n0 + (tx << 2)] = o;
        }
    }
}

// ---------------------------------------------------------------------------
// Flash attention, fp32. One CTA per (batch, head, 64-row q tile).
// 256 threads = 16x16; thread (ty,tx) owns rows ty*4..+3, cols tx*4..+3.
// Per-row softmax stats (m, l) live in registers, replicated across the
// 16-lane row group; reductions via __shfl_xor (offsets < 16 stay in group).
// ---------------------------------------------------------------------------
__global__ __launch_bounds__(256)
void attn_kernel(float* __restrict__ ctx)
{
    extern __shared__ float sm[];
    float* Qt = sm;              // [64 d][68]  Qt[d][r]  (pre-scaled by 1/8)
    float* Kt = sm + 64*68;      // [64 d][68]  Kt[d][c]
    float* Vs = sm + 2*64*68;    // [64 kk][68] Vs[kk][d]
    float* Ps = sm + 3*64*68;    // [64 r][68]  P[r][kk]

    const int b  = blockIdx.z;
    const int h  = blockIdx.y;
    const int q0 = blockIdx.x << 6;
    const int tid = threadIdx.x;
    const int tx = tid & 15;
    const int ty = tid >> 4;
    const int lr = tid >> 2;
    const int lc = (tid & 3) << 2;

    const size_t head_off = (size_t)(b*HEADS + h) * SEQ * DK;
    const float* Qg = g_qh + head_off + (size_t)q0 * DK;
    const float* Kg = g_kh + head_off;
    const float* Vg = g_vh + head_off;

    // Load Q tile transposed (d-major), pre-scaled
    #pragma unroll
    for (int it = 0; it < 4; ++it) {
        int c = lc + (it << 4);
        float4 qv = *(const float4*)(Qg + (size_t)lr * DK + c);
        Qt[(c+0)*68 + lr] = qv.x * QK_SCALE;
        Qt[(c+1)*68 + lr] = qv.y * QK_SCALE;
        Qt[(c+2)*68 + lr] = qv.z * QK_SCALE;
        Qt[(c+3)*68 + lr] = qv.w * QK_SCALE;
    }

    float o[4][4]  = {};
    float mrow[4]  = {-1e30f, -1e30f, -1e30f, -1e30f};
    float lrow[4]  = {};

    for (int kt = 0; kt < SEQ/64; ++kt) {
        const float* Kp = Kg + (size_t)(kt << 6) * DK;
        const float* Vp = Vg + (size_t)(kt << 6) * DK;
        #pragma unroll
        for (int it = 0; it < 4; ++it) {
            int c = lc + (it << 4);
            float4 kv = *(const float4*)(Kp + (size_t)lr * DK + c);
            Kt[(c+0)*68 + lr] = kv.x;
            Kt[(c+1)*68 + lr] = kv.y;
            Kt[(c+2)*68 + lr] = kv.z;
            Kt[(c+3)*68 + lr] = kv.w;
            float4 vv = *(const float4*)(Vp + (size_t)lr * DK + c);
            *(float4*)&Vs[lr*68 + c] = vv;
        }
        __syncthreads();

        // S = (Q*scale) @ K^T : 64x64x64
        float s[4][4] = {};
        #pragma unroll 16
        for (int d = 0; d < 64; ++d) {
            float4 qa = *(const float4*)&Qt[d*68 + (ty << 2)];
            float4 kb = *(const float4*)&Kt[d*68 + (tx << 2)];
            float av[4] = {qa.x, qa.y, qa.z, qa.w};
            float bv[4] = {kb.x, kb.y, kb.z, kb.w};
            #pragma unroll
            for (int i = 0; i < 4; ++i)
                #pragma unroll
                for (int j = 0; j < 4; ++j)
                    s[i][j] += av[i] * bv[j];
        }

        // Online softmax per row (stats in registers, shfl across the 16-lane group)
        #pragma unroll
        for (int i = 0; i < 4; ++i) {
            float rm = fmaxf(fmaxf(s[i][0], s[i][1]), fmaxf(s[i][2], s[i][3]));
            #pragma unroll
            for (int off = 8; off > 0; off >>= 1)
                rm = fmaxf(rm, __shfl_xor_sync(0xffffffffu, rm, off));
            float mo = mrow[i];
            float mn = fmaxf(mo, rm);
            float f  = __expf(mo - mn);
            float p0 = __expf(s[i][0] - mn);
            float p1 = __expf(s[i][1] - mn);
            float p2 = __expf(s[i][2] - mn);
            float p3 = __expf(s[i][3] - mn);
            *(float4*)&Ps[((ty<<2)+i)*68 + (tx<<2)] = make_float4(p0, p1, p2, p3);
            float ps = p0 + p1 + p2 + p3;
            #pragma unroll
            for (int off = 8; off > 0; off >>= 1)
                ps += __shfl_xor_sync(0xffffffffu, ps, off);
            lrow[i] = lrow[i] * f + ps;
            mrow[i] = mn;
            #pragma unroll
            for (int j = 0; j < 4; ++j) o[i][j] *= f;
        }
        __syncthreads();

        // O += P @ V : 64x64x64
        #pragma unroll 8
        for (int k4 = 0; k4 < 16; ++k4) {
            float pr[4][4];
            #pragma unroll
            for (int i = 0; i < 4; ++i) {
                float4 pv = *(const float4*)&Ps[((ty<<2)+i)*68 + (k4<<2)];
                pr[i][0] = pv.x; pr[i][1] = pv.y; pr[i][2] = pv.z; pr[i][3] = pv.w;
            }
            #pragma unroll
            for (int t = 0; t < 4; ++t) {
                float4 vv = *(const float4*)&Vs[((k4<<2)+t)*68 + (tx<<2)];
                float vb[4] = {vv.x, vv.y, vv.z, vv.w};
                #pragma unroll
                for (int i = 0; i < 4; ++i)
                    #pragma unroll
                    for (int j = 0; j < 4; ++j)
                        o[i][j] += pr[i][t] * vb[j];
            }
        }
        __syncthreads();
    }

    // Normalize and write ctx in [B, S, heads*d] layout (un-transpose for free)
    #pragma unroll
    for (int i = 0; i < 4; ++i) {
        int r = (ty << 2) + i;
        float inv = 1.0f / lrow[i];
        float4 ov = make_float4(o[i][0]*inv, o[i][1]*inv, o[i][2]*inv, o[i][3]*inv);
        *(float4*)&ctx[(size_t)(b*SEQ + q0 + r) * HID + h*DK + (tx<<2)] = ov;
    }
}

// ---------------------------------------------------------------------------
extern "C" void kernel_launch(void* const* d_in, const int* in_sizes, int n_in,
                              void* d_out, int out_size)
{
    const float* q  = (const float*)d_in[0];
    const float* k  = (const float*)d_in[1];
    const float* v  = (const float*)d_in[2];
    const float* Wq = (const float*)d_in[3];
    const float* bq = (const float*)d_in[4];
    const float* Wk = (const float*)d_in[5];
    const float* bk = (const float*)d_in[6];
    const float* Wv = (const float*)d_in[7];
    const float* bv = (const float*)d_in[8];
    const float* Wo = (const float*)d_in[9];
    const float* bo = (const float*)d_in[10];

    float *qh, *kh, *vh, *ctx;
    cudaGetSymbolAddress((void**)&qh,  g_qh);
    cudaGetSymbolAddress((void**)&kh,  g_kh);
    cudaGetSymbolAddress((void**)&vh,  g_vh);
    cudaGetSymbolAddress((void**)&ctx, g_ctx);

    const size_t attn_smem = (size_t)4 * 64 * 68 * sizeof(float);  // 69632 B
    cudaFuncSetAttribute(attn_kernel,
                         cudaFuncAttributeMaxDynamicSharedMemorySize,
                         (int)attn_smem);

    dim3 ggrid(HID/64, MROWS/64);   // (16, 64)
    gemm_kernel<1><<<ggrid, 256>>>(q, Wq, bq, qh);
    gemm_kernel<1><<<ggrid, 256>>>(k, Wk, bk, kh);
    gemm_kernel<1><<<ggrid, 256>>>(v, Wv, bv, vh);
    attn_kernel<<<dim3(SEQ/64, HEADS, BATCH), 256, attn_smem>>>(ctx);
    gemm_kernel<0><<<ggrid, 256>>>(ctx, Wo, bo, (float*)d_out);
}

// round 3
// speedup vs baseline: 1.7807x; 1.7807x over previous
#include <cuda_runtime.h>

#define HID   1024
#define HEADS 16
#define DK    64
#define BATCH 2
#define SEQ   2048
#define MROWS (BATCH*SEQ)      // 4096

// Scratch (allocation-free rule: __device__ globals)
__device__ float g_qh[BATCH*HEADS*SEQ*DK];   // [B,h,S,d]
__device__ float g_kh[BATCH*HEADS*SEQ*DK];
__device__ float g_vh[BATCH*HEADS*SEQ*DK];
__device__ float g_ctx[MROWS*HID];           // [B,S,H]

// ---------------------------------------------------------------------------
// tf32 helpers
// ---------------------------------------------------------------------------
__device__ __forceinline__ unsigned f2t(float x) {
    unsigned r; asm("cvt.rna.tf32.f32 %0, %1;" : "=r"(r) : "f"(x)); return r;
}
__device__ __forceinline__ float f2tf(float x) { return __uint_as_float(f2t(x)); }

// D = A(16x8,row) * B(8x8,col) + D ; tf32 inputs, f32 accum
__device__ __forceinline__ void mma8(float* c, const unsigned* a, const unsigned* b) {
    asm volatile(
        "mma.sync.aligned.m16n8k8.row.col.f32.tf32.tf32.f32 "
        "{%0,%1,%2,%3}, {%4,%5,%6,%7}, {%8,%9}, {%0,%1,%2,%3};"
        : "+f"(c[0]), "+f"(c[1]), "+f"(c[2]), "+f"(c[3])
        : "r"(a[0]), "r"(a[1]), "r"(a[2]), "r"(a[3]), "r"(b[0]), "r"(b[1]));
}

// ---------------------------------------------------------------------------
// C[M,N] = X[M,K] @ W[N,K]^T + bias  (M=4096, N=K=1024), tf32 tensor cores.
// 128x128 block tile, BK=32, 256 threads = 8 warps (2m x 4n), warp tile 64x32.
// smem k-major [k][128+4]: frag loads conflict-free (stride 132 = 4 mod 32).
// ---------------------------------------------------------------------------
template<int SCATTER>
__global__ __launch_bounds__(256)
void gemm_tc(const float* __restrict__ X, const float* __restrict__ W,
             const float* __restrict__ bias, float* __restrict__ out)
{
    __shared__ float As[32][132];   // [k][m]
    __shared__ float Bs[32][132];   // [k][n]
    const int tid  = threadIdx.x;
    const int lane = tid & 31;
    const int wid  = tid >> 5;
    const int wm   = wid >> 2;        // 0..1
    const int wn   = wid & 3;         // 0..3
    const int ql   = lane >> 2;       // groupID 0..7
    const int qc   = lane & 3;        // tid-in-group
    const int m0 = blockIdx.y << 7;
    const int n0 = blockIdx.x << 7;

    // loaders: row = tid&127 (warp = 32 consecutive rows -> conflict-free STS),
    // k-offset = (tid>>7)*16, 4 float4 each
    const int lr = tid & 127;
    const int lk = (tid >> 7) << 4;
    const float* Ap = X + (size_t)(m0 + lr) * HID + lk;
    const float* Bp = W + (size_t)(n0 + lr) * HID + lk;

    float acc[4][4][4] = {};

    float4 pa[4], pb[4];
    #pragma unroll
    for (int i = 0; i < 4; ++i) {
        pa[i] = *(const float4*)(Ap + i*4);
        pb[i] = *(const float4*)(Bp + i*4);
    }

    for (int kt = 0; kt < HID/32; ++kt) {
        #pragma unroll
        for (int i = 0; i < 4; ++i) {
            int kk = lk + i*4;
            As[kk+0][lr] = f2tf(pa[i].x); As[kk+1][lr] = f2tf(pa[i].y);
            As[kk+2][lr] = f2tf(pa[i].z); As[kk+3][lr] = f2tf(pa[i].w);
            Bs[kk+0][lr] = f2tf(pb[i].x); Bs[kk+1][lr] = f2tf(pb[i].y);
            Bs[kk+2][lr] = f2tf(pb[i].z); Bs[kk+3][lr] = f2tf(pb[i].w);
        }
        __syncthreads();
        if (kt + 1 < HID/32) {
            #pragma unroll
            for (int i = 0; i < 4; ++i) {
                pa[i] = *(const float4*)(Ap + (kt+1)*32 + i*4);
                pb[i] = *(const float4*)(Bp + (kt+1)*32 + i*4);
            }
        }
        #pragma unroll
        for (int ks = 0; ks < 4; ++ks) {
            const int k0 = ks << 3;
            unsigned af[4][4], bf[4][2];
            #pragma unroll
            for (int mf = 0; mf < 4; ++mf) {
                int mr = wm*64 + mf*16 + ql;
                af[mf][0] = __float_as_uint(As[k0+qc  ][mr  ]);
                af[mf][1] = __float_as_uint(As[k0+qc  ][mr+8]);
                af[mf][2] = __float_as_uint(As[k0+qc+4][mr  ]);
                af[mf][3] = __float_as_uint(As[k0+qc+4][mr+8]);
            }
            #pragma unroll
            for (int nf = 0; nf < 4; ++nf) {
                int nc = wn*32 + nf*8 + ql;
                bf[nf][0] = __float_as_uint(Bs[k0+qc  ][nc]);
                bf[nf][1] = __float_as_uint(Bs[k0+qc+4][nc]);
            }
            #pragma unroll
            for (int mf = 0; mf < 4; ++mf)
                #pragma unroll
                for (int nf = 0; nf < 4; ++nf)
                    mma8(acc[mf][nf], af[mf], bf[nf]);
        }
        __syncthreads();
    }

    // epilogue: c0,c1 -> row ql, cols 2qc,2qc+1 ; c2,c3 -> row ql+8
    #pragma unroll
    for (int mf = 0; mf < 4; ++mf) {
        int mlo = m0 + wm*64 + mf*16 + ql;
        #pragma unroll
        for (int nf = 0; nf < 4; ++nf) {
            int col = n0 + wn*32 + nf*8 + 2*qc;
            float2 bb = *(const float2*)&bias[col];
            float2 v0 = make_float2(acc[mf][nf][0] + bb.x, acc[mf][nf][1] + bb.y);
            float2 v1 = make_float2(acc[mf][nf][2] + bb.x, acc[mf][nf][3] + bb.y);
            if (SCATTER) {
                int hh = col >> 6, d = col & 63;
                int ma = mlo, mb = mlo + 8;
                *(float2*)&out[(size_t)(((ma>>11)*HEADS + hh)*SEQ + (ma & (SEQ-1)))*DK + d] = v0;
                *(float2*)&out[(size_t)(((mb>>11)*HEADS + hh)*SEQ + (mb & (SEQ-1)))*DK + d] = v1;
            } else {
                *(float2*)&out[(size_t)mlo    *HID + col] = v0;
                *(float2*)&out[(size_t)(mlo+8)*HID + col] = v1;
            }
        }
    }
}

// ---------------------------------------------------------------------------
// Flash attention with tf32 mma. CTA = (b, h, 128-row q tile), 8 warps.
// Warp w owns q rows w*16..w*16+15. Q fragments live in registers for the
// whole KV loop. K stored [d][68] (B-frag for QK^T), V stored [k][68]
// (B-frag for PV), P staged through smem [128][68].
// ---------------------------------------------------------------------------
__global__ __launch_bounds__(256)
void attn_tc(float* __restrict__ ctx)
{
    extern __shared__ float sm[];
    float* Kt = sm;              // [64 d][68]  Kt[d][s]
    float* Vs = sm + 64*68;      // [64 k][68]  Vs[k][d]
    float* Ps = sm + 2*64*68;    // [128 q][68] P[q][k]

    const int b  = blockIdx.z;
    const int h  = blockIdx.y;
    const int q0 = blockIdx.x << 7;
    const int tid  = threadIdx.x;
    const int lane = tid & 31;
    const int wid  = tid >> 5;
    const int ql = lane >> 2;
    const int qc = lane & 3;
    const int lr = tid >> 2;          // 0..63
    const int lc = (tid & 3) << 2;    // 0,4,8,12

    const size_t hoff = (size_t)(b*HEADS + h) * SEQ * DK;
    const float* Qg = g_qh + hoff + (size_t)(q0 + wid*16) * DK;
    const float* Kg = g_kh + hoff;
    const float* Vg = g_vh + hoff;

    // Q fragments in registers, pre-scaled by 1/sqrt(dk)
    unsigned qf[8][4];
    #pragma unroll
    for (int ks = 0; ks < 8; ++ks) {
        int c = ks*8 + qc;
        qf[ks][0] = f2t(Qg[(size_t)(ql  )*DK + c    ] * 0.125f);
        qf[ks][1] = f2t(Qg[(size_t)(ql+8)*DK + c    ] * 0.125f);
        qf[ks][2] = f2t(Qg[(size_t)(ql  )*DK + c + 4] * 0.125f);
        qf[ks][3] = f2t(Qg[(size_t)(ql+8)*DK + c + 4] * 0.125f);
    }

    float oacc[8][4] = {};
    float mA = -1e30f, mB = -1e30f, lA = 0.f, lB = 0.f;

    for (int kt = 0; kt < SEQ/64; ++kt) {
        const float* Kp = Kg + (size_t)(kt << 6) * DK;
        const float* Vp = Vg + (size_t)(kt << 6) * DK;
        #pragma unroll
        for (int i = 0; i < 4; ++i) {
            int c = lc + (i << 4);
            float4 kv = *(const float4*)(Kp + (size_t)lr*DK + c);
            Kt[(c+0)*68 + lr] = f2tf(kv.x);
            Kt[(c+1)*68 + lr] = f2tf(kv.y);
            Kt[(c+2)*68 + lr] = f2tf(kv.z);
            Kt[(c+3)*68 + lr] = f2tf(kv.w);
            float4 vv = *(const float4*)(Vp + (size_t)lr*DK + c);
            *(float4*)&Vs[lr*68 + c] =
                make_float4(f2tf(vv.x), f2tf(vv.y), f2tf(vv.z), f2tf(vv.w));
        }
        __syncthreads();

        // S = Q @ K^T  (128x64 per CTA; 16x64 per warp)
        float sacc[8][4] = {};
        #pragma unroll
        for (int ks = 0; ks < 8; ++ks) {
            #pragma unroll
            for (int nf = 0; nf < 8; ++nf) {
                unsigned bf[2];
                bf[0] = __float_as_uint(Kt[(ks*8+qc  )*68 + nf*8 + ql]);
                bf[1] = __float_as_uint(Kt[(ks*8+qc+4)*68 + nf*8 + ql]);
                mma8(sacc[nf], qf[ks], bf);
            }
        }

        // online softmax: row A = ql, row B = ql+8 (per lane, quad-replicated)
        float rmA = -1e30f, rmB = -1e30f;
        #pragma unroll
        for (int nf = 0; nf < 8; ++nf) {
            rmA = fmaxf(rmA, fmaxf(sacc[nf][0], sacc[nf][1]));
            rmB = fmaxf(rmB, fmaxf(sacc[nf][2], sacc[nf][3]));
        }
        rmA = fmaxf(rmA, __shfl_xor_sync(0xffffffffu, rmA, 1));
        rmA = fmaxf(rmA, __shfl_xor_sync(0xffffffffu, rmA, 2));
        rmB = fmaxf(rmB, __shfl_xor_sync(0xffffffffu, rmB, 1));
        rmB = fmaxf(rmB, __shfl_xor_sync(0xffffffffu, rmB, 2));
        float mnA = fmaxf(mA, rmA), mnB = fmaxf(mB, rmB);
        float fA = __expf(mA - mnA), fB = __expf(mB - mnB);
        float rsA = 0.f, rsB = 0.f;
        #pragma unroll
        for (int nf = 0; nf < 8; ++nf) {
            float p0 = __expf(sacc[nf][0] - mnA);
            float p1 = __expf(sacc[nf][1] - mnA);
            float p2 = __expf(sacc[nf][2] - mnB);
            float p3 = __expf(sacc[nf][3] - mnB);
            rsA += p0 + p1; rsB += p2 + p3;
            int colb = nf*8 + 2*qc;
            *(float2*)&Ps[(wid*16 + ql  )*68 + colb] = make_float2(f2tf(p0), f2tf(p1));
            *(float2*)&Ps[(wid*16 + ql+8)*68 + colb] = make_float2(f2tf(p2), f2tf(p3));
        }
        rsA += __shfl_xor_sync(0xffffffffu, rsA, 1);
        rsA += __shfl_xor_sync(0xffffffffu, rsA, 2);
        rsB += __shfl_xor_sync(0xffffffffu, rsB, 1);
        rsB += __shfl_xor_sync(0xffffffffu, rsB, 2);
        lA = lA*fA + rsA;  lB = lB*fB + rsB;
        mA = mnA;          mB = mnB;
        #pragma unroll
        for (int df = 0; df < 8; ++df) {
            oacc[df][0] *= fA; oacc[df][1] *= fA;
            oacc[df][2] *= fB; oacc[df][3] *= fB;
        }
        __syncwarp();   // P rows are warp-private; make STS visible to lane mates

        // O += P @ V  (16x64 per warp)
        #pragma unroll
        for (int ks = 0; ks < 8; ++ks) {
            unsigned pf[4];
            pf[0] = __float_as_uint(Ps[(wid*16 + ql  )*68 + ks*8 + qc    ]);
            pf[1] = __float_as_uint(Ps[(wid*16 + ql+8)*68 + ks*8 + qc    ]);
            pf[2] = __float_as_uint(Ps[(wid*16 + ql  )*68 + ks*8 + qc + 4]);
            pf[3] = __float_as_uint(Ps[(wid*16 + ql+8)*68 + ks*8 + qc + 4]);
            #pragma unroll
            for (int df = 0; df < 8; ++df) {
                unsigned bv[2];
                bv[0] = __float_as_uint(Vs[(ks*8+qc  )*68 + df*8 + ql]);
                bv[1] = __float_as_uint(Vs[(ks*8+qc+4)*68 + df*8 + ql]);
                mma8(oacc[df], pf, bv);
            }
        }
        __syncthreads();
    }

    // normalize + write ctx [B,S,H]
    float iA = 1.0f / lA, iB = 1.0f / lB;
    int rowA = b*SEQ + q0 + wid*16 + ql;
    #pragma unroll
    for (int df = 0; df < 8; ++df) {
        int col = h*DK + df*8 + 2*qc;
        *(float2*)&ctx[(size_t)rowA    *HID + col] =
            make_float2(oacc[df][0]*iA, oacc[df][1]*iA);
        *(float2*)&ctx[(size_t)(rowA+8)*HID + col] =
            make_float2(oacc[df][2]*iB, oacc[df][3]*iB);
    }
}

// ---------------------------------------------------------------------------
extern "C" void kernel_launch(void* const* d_in, const int* in_sizes, int n_in,
                              void* d_out, int out_size)
{
    const float* q  = (const float*)d_in[0];
    const float* k  = (const float*)d_in[1];
    const float* v  = (const float*)d_in[2];
    const float* Wq = (const float*)d_in[3];
    const float* bq = (const float*)d_in[4];
    const float* Wk = (const float*)d_in[5];
    const float* bk = (const float*)d_in[6];
    const float* Wv = (const float*)d_in[7];
    const float* bv = (const float*)d_in[8];
    const float* Wo = (const float*)d_in[9];
    const float* bo = (const float*)d_in[10];

    float *qh, *kh, *vh, *ctx;
    cudaGetSymbolAddress((void**)&qh,  g_qh);
    cudaGetSymbolAddress((void**)&kh,  g_kh);
    cudaGetSymbolAddress((void**)&vh,  g_vh);
    cudaGetSymbolAddress((void**)&ctx, g_ctx);

    const size_t attn_smem = (size_t)(2*64*68 + 128*68) * sizeof(float);  // 69632
    cudaFuncSetAttribute(attn_tc,
                         cudaFuncAttributeMaxDynamicSharedMemorySize,
                         (int)attn_smem);

    dim3 ggrid(HID/128, MROWS/128);   // (8, 32)
    gemm_tc<1><<<ggrid, 256>>>(q, Wq, bq, qh);
    gemm_tc<1><<<ggrid, 256>>>(k, Wk, bk, kh);
    gemm_tc<1><<<ggrid, 256>>>(v, Wv, bv, vh);
    attn_tc<<<dim3(SEQ/128, HEADS, BATCH), 256, attn_smem>>>(ctx);
    gemm_tc<0><<<ggrid, 256>>>(ctx, Wo, bo, (float*)d_out);
}